// round 1
// baseline (speedup 1.0000x reference)
#include <cuda_runtime.h>
#include <math.h>
#include <stdint.h>

#define Bb 8
#define Nn 1024
#define Ee 256
#define Hh 4
#define Uu 6
#define Oo 8
#define LAMBDA_INIT 0.63212055882855767840f

// ---------------- scratch (static device memory; no allocation) ----------------
__device__ unsigned char g_maskT[(size_t)Bb * Nn * Nn];          // 8 MB
__device__ float g_v[(size_t)Bb * Nn * Ee];                      // 8 MB  v[b][n][h*64+d]
__device__ float g_outpre[(size_t)Bb * Nn * Ee];                 // 8 MB
__device__ float g_m[(size_t)Bb * Oo * Nn];
__device__ float g_l[(size_t)Bb * Oo * Nn];
__device__ float g_beta;
__device__ int   g_mask_kind;                                    // 0=u8, 1=i32, 2=f32

// ---------------- f32x2 helpers ----------------
__device__ __forceinline__ unsigned long long pack2(float a, float b) {
    unsigned long long r;
    asm("mov.b64 %0, {%1,%2};" : "=l"(r) : "f"(a), "f"(b));
    return r;
}
__device__ __forceinline__ float2 unpack2(unsigned long long v) {
    float2 r;
    asm("mov.b64 {%0,%1}, %2;" : "=f"(r.x), "=f"(r.y) : "l"(v));
    return r;
}
__device__ __forceinline__ unsigned long long ffma2(unsigned long long a,
                                                    unsigned long long b,
                                                    unsigned long long c) {
    unsigned long long d;
    asm("fma.rn.f32x2 %0, %1, %2, %3;" : "=l"(d) : "l"(a), "l"(b), "l"(c));
    return d;
}

// ---------------- K0: beta ----------------
__global__ void beta_kernel(const float* __restrict__ lq, const float* __restrict__ lk,
                            float* __restrict__ beta_slot) {
    __shared__ float red[128];
    int t = threadIdx.x;
    float s = (t < 100) ? lq[t] * lk[t] : 0.f;
    red[t] = s;
    __syncthreads();
    for (int st = 64; st > 0; st >>= 1) {
        if (t < st) red[t] += red[t + st];
        __syncthreads();
    }
    if (t == 0) {
        float lam1 = expf(red[0]);
        float z = lam1 * LAMBDA_INIT;
        float beta = 1.f / (1.f + expf(-z));
        g_beta = beta;
        *beta_slot = beta;
    }
}

// ---------------- K1: mask dtype sniffer ----------------
// Classify from nonzero byte positions mod 4 over the first 16KB:
//   int32 (0/1): nz only at residue 0.   float32 (0.0/1.0f = 00 00 80 3F): nz only at residues 2,3.
//   u8/bool: nz spread across residues.
__global__ void detect_kernel(const unsigned char* __restrict__ raw) {
    __shared__ int cnt[4];
    if (threadIdx.x < 4) cnt[threadIdx.x] = 0;
    __syncthreads();
    for (int i = threadIdx.x; i < 16384; i += blockDim.x)
        if (raw[i]) atomicAdd(&cnt[i & 3], 1);
    __syncthreads();
    if (threadIdx.x == 0) {
        int kind;
        if (cnt[1] == 0 && cnt[2] == 0 && cnt[3] == 0) kind = 1;       // int32
        else if (cnt[0] == 0 && cnt[1] == 0)           kind = 2;       // float32
        else                                            kind = 0;       // bytes
        g_mask_kind = kind;
    }
}

// ---------------- K2: mask transpose  maskT[b][i][j] = (umask[b][j][i] != 0) ----------------
__global__ void mask_transpose_kernel(const void* __restrict__ rawv) {
    __shared__ unsigned char tile[32][33];
    int b = blockIdx.z;
    int i0 = blockIdx.x * 32, j0 = blockIdx.y * 32;
    int tx = threadIdx.x, ty = threadIdx.y;
    int kind = g_mask_kind;
    size_t src = ((size_t)b * Nn + (j0 + ty)) * Nn + (i0 + tx);
    unsigned char v;
    if (kind == 0)      v = (((const unsigned char*)rawv)[src] != 0);
    else if (kind == 1) v = (((const int*)rawv)[src] != 0);
    else                v = (((const float*)rawv)[src] != 0.f);
    tile[ty][tx] = v;
    __syncthreads();
    g_maskT[((size_t)b * Nn + (i0 + ty)) * Nn + (j0 + tx)] = tile[tx][ty];
}

// ---------------- gemm: Y[row,f] = sum_e X[row,e] * W[f,e]   (rows=8192, E=256) ----------------
__global__ __launch_bounds__(256) void gemm_xw_kernel(const float* __restrict__ X,
                                                      const float* __restrict__ W,
                                                      float* __restrict__ Y) {
    __shared__ float As[64][65];   // X tile [row][e]
    __shared__ float Bs[64][65];   // W tile transposed: Bs[e][f]
    int t = threadIdx.x;
    int row0 = blockIdx.x * 64;
    int col0 = blockIdx.y * 64;
    int rgp = t >> 4;    // rows rgp*4 .. +3
    int cg  = t & 15;    // cols cg*4 .. +3
    unsigned long long acc[4][2];
#pragma unroll
    for (int r = 0; r < 4; r++) { acc[r][0] = 0ULL; acc[r][1] = 0ULL; }

    for (int k0 = 0; k0 < Ee; k0 += 64) {
#pragma unroll
        for (int q = 0; q < 4; q++) {
            int idx = t + q * 256;
            int r = idx >> 4, e4 = (idx & 15) * 4;
            float4 v = *(const float4*)(X + (size_t)(row0 + r) * Ee + k0 + e4);
            As[r][e4 + 0] = v.x; As[r][e4 + 1] = v.y; As[r][e4 + 2] = v.z; As[r][e4 + 3] = v.w;
        }
#pragma unroll
        for (int q = 0; q < 4; q++) {
            int idx = t + q * 256;
            int f = idx >> 4, e4 = (idx & 15) * 4;
            float4 v = *(const float4*)(W + (size_t)(col0 + f) * Ee + k0 + e4);
            Bs[e4 + 0][f] = v.x; Bs[e4 + 1][f] = v.y; Bs[e4 + 2][f] = v.z; Bs[e4 + 3][f] = v.w;
        }
        __syncthreads();
#pragma unroll 8
        for (int k = 0; k < 64; k++) {
            float b0 = Bs[k][cg * 4 + 0], b1 = Bs[k][cg * 4 + 1];
            float b2 = Bs[k][cg * 4 + 2], b3 = Bs[k][cg * 4 + 3];
            unsigned long long blo = pack2(b0, b1);
            unsigned long long bhi = pack2(b2, b3);
#pragma unroll
            for (int r = 0; r < 4; r++) {
                float a = As[rgp * 4 + r][k];
                unsigned long long a2 = pack2(a, a);
                acc[r][0] = ffma2(a2, blo, acc[r][0]);
                acc[r][1] = ffma2(a2, bhi, acc[r][1]);
            }
        }
        __syncthreads();
    }
#pragma unroll
    for (int r = 0; r < 4; r++) {
        float2 lo = unpack2(acc[r][0]);
        float2 hi = unpack2(acc[r][1]);
        float4 o = make_float4(lo.x, lo.y, hi.x, hi.y);
        *(float4*)(Y + (size_t)(row0 + rgp * 4 + r) * Ee + col0 + cg * 4) = o;
    }
}

// ---------------- K4: softmax stats (m, l) per (b, o, i) ----------------
__global__ __launch_bounds__(256) void stats_kernel(const float* __restrict__ u,
                                                    const float* __restrict__ u_w,
                                                    const float* __restrict__ u_b) {
    int i = blockIdx.x, b = blockIdx.y;
    int t = threadIdx.x;
    __shared__ float s_uw[48], s_ub[8], s_m[8];
    __shared__ float red[8 * 256];
    if (t < 48) s_uw[t] = u_w[t];
    if (t < 8)  s_ub[t] = u_b[t];
    __syncthreads();

    const float NEG_INF = __int_as_float(0xff800000);
    int j0 = t * 4;
    unsigned int mword = *(const unsigned int*)(g_maskT + ((size_t)b * Nn + i) * Nn + j0);
    float uu[4][Uu];
#pragma unroll
    for (int c = 0; c < Uu; c++) {
        float4 v = *(const float4*)(u + ((size_t)(b * Uu + c) * Nn + i) * Nn + j0);
        uu[0][c] = v.x; uu[1][c] = v.y; uu[2][c] = v.z; uu[3][c] = v.w;
    }
    float sv[4][Oo];
#pragma unroll
    for (int q = 0; q < 4; q++) {
        bool masked = ((mword >> (q * 8)) & 0xFF) != 0;
#pragma unroll
        for (int o = 0; o < Oo; o++) {
            float s = s_ub[o];
#pragma unroll
            for (int c = 0; c < Uu; c++) s = fmaf(s_uw[o * Uu + c], uu[q][c], s);
            sv[q][o] = masked ? NEG_INF : s;
        }
    }
#pragma unroll
    for (int o = 0; o < Oo; o++)
        red[o * 256 + t] = fmaxf(fmaxf(sv[0][o], sv[1][o]), fmaxf(sv[2][o], sv[3][o]));
    __syncthreads();
    for (int st = 128; st >= 1; st >>= 1) {
        if (t < st) {
#pragma unroll
            for (int o = 0; o < Oo; o++)
                red[o * 256 + t] = fmaxf(red[o * 256 + t], red[o * 256 + t + st]);
        }
        __syncthreads();
    }
    if (t < 8) s_m[t] = red[t * 256];
    __syncthreads();

    float se[Oo];
#pragma unroll
    for (int o = 0; o < Oo; o++) {
        float m = s_m[o];
        float acc = 0.f;
#pragma unroll
        for (int q = 0; q < 4; q++)
            if (sv[q][o] != NEG_INF) acc += __expf(sv[q][o] - m);
        se[o] = acc;
    }
    __syncthreads();
#pragma unroll
    for (int o = 0; o < Oo; o++) red[o * 256 + t] = se[o];
    __syncthreads();
    for (int st = 128; st >= 1; st >>= 1) {
        if (t < st) {
#pragma unroll
            for (int o = 0; o < Oo; o++)
                red[o * 256 + t] += red[o * 256 + t + st];
        }
        __syncthreads();
    }
    if (t < 8) {
        g_m[((size_t)b * Oo + t) * Nn + i] = s_m[t];
        g_l[((size_t)b * Oo + t) * Nn + i] = red[t * 256];
    }
}

// ---------------- K5: attn_w = p[2h] - beta*p[2h+1], written to output ----------------
__global__ __launch_bounds__(256) void attnw_kernel(const float* __restrict__ u,
                                                    const float* __restrict__ u_w,
                                                    const float* __restrict__ u_b,
                                                    float* __restrict__ attn_out) {
    int i = blockIdx.x, b = blockIdx.y;
    int t = threadIdx.x;
    __shared__ float s_uw[48], s_ub[8], s_m[8], s_rl[8], s_beta;
    if (t < 48) s_uw[t] = u_w[t];
    if (t < 8) {
        s_ub[t] = u_b[t];
        s_m[t]  = g_m[((size_t)b * Oo + t) * Nn + i];
        s_rl[t] = 1.f / g_l[((size_t)b * Oo + t) * Nn + i];
    }
    if (t == 0) s_beta = g_beta;
    __syncthreads();

    int j0 = t * 4;
    unsigned int mword = *(const unsigned int*)(g_maskT + ((size_t)b * Nn + i) * Nn + j0);
    float uu[4][Uu];
#pragma unroll
    for (int c = 0; c < Uu; c++) {
        float4 v = *(const float4*)(u + ((size_t)(b * Uu + c) * Nn + i) * Nn + j0);
        uu[0][c] = v.x; uu[1][c] = v.y; uu[2][c] = v.z; uu[3][c] = v.w;
    }
    float beta = s_beta;
    float wq[Hh][4];
#pragma unroll
    for (int q = 0; q < 4; q++) {
        bool masked = ((mword >> (q * 8)) & 0xFF) != 0;
        float p[Oo];
#pragma unroll
        for (int o = 0; o < Oo; o++) {
            if (masked) { p[o] = 0.f; continue; }
            float s = s_ub[o];
#pragma unroll
            for (int c = 0; c < Uu; c++) s = fmaf(s_uw[o * Uu + c], uu[q][c], s);
            p[o] = __expf(s - s_m[o]) * s_rl[o];
        }
#pragma unroll
        for (int h = 0; h < Hh; h++) wq[h][q] = p[2 * h] - beta * p[2 * h + 1];
    }
#pragma unroll
    for (int h = 0; h < Hh; h++) {
        float4 o = make_float4(wq[h][0], wq[h][1], wq[h][2], wq[h][3]);
        *(float4*)(attn_out + ((size_t)(b * Hh + h) * Nn + i) * Nn + j0) = o;
    }
}

// ---------------- K6: out_pre[b,i,h*64+d] = sum_j attn_w[b,h,i,j] * v[b,j,h*64+d] ----------------
__global__ __launch_bounds__(256) void av_gemm_kernel(const float* __restrict__ A) {
    __shared__ float As[64][65];   // attn tile [i][j]
    __shared__ float Vs[64][64];   // v tile [j][d]
    int t = threadIdx.x;
    int bh = blockIdx.y;
    int b = bh >> 2, h = bh & 3;
    int i0 = blockIdx.x * 64;
    int dg = t & 7;    // d = dg*8 .. +7
    int rg = t >> 3;   // rows rg*2, rg*2+1
    const float* Abase = A + ((size_t)bh * Nn + i0) * Nn;
    const float* Vbase = g_v + (size_t)b * Nn * Ee + h * 64;

    unsigned long long acc[2][4];
#pragma unroll
    for (int r = 0; r < 2; r++)
#pragma unroll
        for (int p = 0; p < 4; p++) acc[r][p] = 0ULL;

    for (int j0 = 0; j0 < Nn; j0 += 64) {
#pragma unroll
        for (int q = 0; q < 4; q++) {   // A tile: 64x64 = 1024 float4
            int idx = t + q * 256;
            int r = idx >> 4, c4 = (idx & 15) * 4;
            float4 v = *(const float4*)(Abase + (size_t)r * Nn + j0 + c4);
            As[r][c4 + 0] = v.x; As[r][c4 + 1] = v.y; As[r][c4 + 2] = v.z; As[r][c4 + 3] = v.w;
        }
#pragma unroll
        for (int q = 0; q < 4; q++) {   // V tile: 64x64
            int idx = t + q * 256;
            int r = idx >> 4, c4 = (idx & 15) * 4;
            float4 v = *(const float4*)(Vbase + (size_t)(j0 + r) * Ee + c4);
            *(float4*)&Vs[r][c4] = v;
        }
        __syncthreads();
#pragma unroll 8
        for (int j = 0; j < 64; j++) {
            float4 va = *(const float4*)&Vs[j][dg * 8];
            float4 vb = *(const float4*)&Vs[j][dg * 8 + 4];
            unsigned long long v0 = pack2(va.x, va.y);
            unsigned long long v1 = pack2(va.z, va.w);
            unsigned long long v2 = pack2(vb.x, vb.y);
            unsigned long long v3 = pack2(vb.z, vb.w);
#pragma unroll
            for (int r = 0; r < 2; r++) {
                float a = As[rg * 2 + r][j];
                unsigned long long a2 = pack2(a, a);
                acc[r][0] = ffma2(a2, v0, acc[r][0]);
                acc[r][1] = ffma2(a2, v1, acc[r][1]);
                acc[r][2] = ffma2(a2, v2, acc[r][2]);
                acc[r][3] = ffma2(a2, v3, acc[r][3]);
            }
        }
        __syncthreads();
    }
#pragma unroll
    for (int r = 0; r < 2; r++) {
        size_t base = ((size_t)b * Nn + i0 + rg * 2 + r) * Ee + h * 64 + dg * 8;
        float2 a0 = unpack2(acc[r][0]), a1 = unpack2(acc[r][1]);
        float2 a2 = unpack2(acc[r][2]), a3 = unpack2(acc[r][3]);
        *(float4*)(g_outpre + base)     = make_float4(a0.x, a0.y, a1.x, a1.y);
        *(float4*)(g_outpre + base + 4) = make_float4(a2.x, a2.y, a3.x, a3.y);
    }
}

// ---------------- launch ----------------
extern "C" void kernel_launch(void* const* d_in, const int* in_sizes, int n_in,
                              void* d_out, int out_size) {
    const float* x     = (const float*)d_in[0];
    const float* u     = (const float*)d_in[1];
    const void*  umask = d_in[2];
    const float* v_w   = (const float*)d_in[3];
    const float* out_w = (const float*)d_in[4];
    const float* u_w   = (const float*)d_in[5];
    const float* u_b   = (const float*)d_in[6];
    const float* lq    = (const float*)d_in[7];
    const float* lk    = (const float*)d_in[8];

    float* out = (float*)d_out;
    const size_t OUT_ELEMS  = (size_t)Bb * Nn * Ee;          // 2097152
    const size_t ATTN_ELEMS = (size_t)Bb * Hh * Nn * Nn;     // 33554432
    float* attn_out  = out + OUT_ELEMS;
    float* beta_slot = out + OUT_ELEMS + ATTN_ELEMS;

    float* vptr = nullptr;
    float* optr = nullptr;
    cudaGetSymbolAddress((void**)&vptr, g_v);
    cudaGetSymbolAddress((void**)&optr, g_outpre);

    beta_kernel<<<1, 128>>>(lq, lk, beta_slot);
    detect_kernel<<<1, 256>>>((const unsigned char*)umask);
    mask_transpose_kernel<<<dim3(32, 32, 8), dim3(32, 32)>>>(umask);
    gemm_xw_kernel<<<dim3(128, 4), 256>>>(x, v_w, vptr);           // v projection
    stats_kernel<<<dim3(Nn, Bb), 256>>>(u, u_w, u_b);
    attnw_kernel<<<dim3(Nn, Bb), 256>>>(u, u_w, u_b, attn_out);
    av_gemm_kernel<<<dim3(16, 32), 256>>>(attn_out);               // attn_w @ v
    gemm_xw_kernel<<<dim3(128, 4), 256>>>(optr, out_w, out);       // output projection
    (void)in_sizes; (void)n_in; (void)out_size;
}

// round 2
// speedup vs baseline: 1.4455x; 1.4455x over previous
#include <cuda_runtime.h>
#include <math.h>
#include <stdint.h>

#define Bb 8
#define Nn 1024
#define Ee 256
#define Hh 4
#define Uu 6
#define Oo 8
#define LAMBDA_INIT 0.63212055882855767840f

typedef unsigned long long ull;

// ---------------- scratch (static device memory; no allocation) ----------------
__device__ unsigned char g_maskT[(size_t)Bb * Nn * Nn];          // 8 MB
__device__ float g_v[(size_t)Bb * Nn * Ee];                      // 8 MB  v[b][n][h*64+d]
__device__ float g_outpre[(size_t)Bb * Nn * Ee];                 // 8 MB
__device__ float g_l[(size_t)Bb * Oo * Nn];                      // softmax denominators
__device__ float g_beta;
__device__ int   g_mask_kind;                                    // 0=u8, 1=i32, 2=f32

// ---------------- f32x2 helpers ----------------
__device__ __forceinline__ ull pack2(float a, float b) {
    ull r;
    asm("mov.b64 %0, {%1,%2};" : "=l"(r) : "f"(a), "f"(b));
    return r;
}
__device__ __forceinline__ float2 unpack2(ull v) {
    float2 r;
    asm("mov.b64 {%0,%1}, %2;" : "=f"(r.x), "=f"(r.y) : "l"(v));
    return r;
}
__device__ __forceinline__ ull ffma2(ull a, ull b, ull c) {
    ull d;
    asm("fma.rn.f32x2 %0, %1, %2, %3;" : "=l"(d) : "l"(a), "l"(b), "l"(c));
    return d;
}

// ---------------- K0: beta ----------------
__global__ void beta_kernel(const float* __restrict__ lq, const float* __restrict__ lk,
                            float* __restrict__ beta_slot) {
    __shared__ float red[128];
    int t = threadIdx.x;
    float s = (t < 100) ? lq[t] * lk[t] : 0.f;
    red[t] = s;
    __syncthreads();
    for (int st = 64; st > 0; st >>= 1) {
        if (t < st) red[t] += red[t + st];
        __syncthreads();
    }
    if (t == 0) {
        float lam1 = expf(red[0]);
        float z = lam1 * LAMBDA_INIT;
        float beta = 1.f / (1.f + expf(-z));
        g_beta = beta;
        *beta_slot = beta;
    }
}

// ---------------- K1: mask dtype sniffer ----------------
__global__ void detect_kernel(const unsigned char* __restrict__ raw) {
    __shared__ int cnt[4];
    if (threadIdx.x < 4) cnt[threadIdx.x] = 0;
    __syncthreads();
    for (int i = threadIdx.x; i < 16384; i += blockDim.x)
        if (raw[i]) atomicAdd(&cnt[i & 3], 1);
    __syncthreads();
    if (threadIdx.x == 0) {
        int kind;
        if (cnt[1] == 0 && cnt[2] == 0 && cnt[3] == 0) kind = 1;       // int32
        else if (cnt[0] == 0 && cnt[1] == 0)           kind = 2;       // float32
        else                                            kind = 0;       // bytes
        g_mask_kind = kind;
    }
}

// ---------------- K2: mask transpose  maskT[b][i][j] = (umask[b][j][i] != 0) ----------------
__global__ void mask_transpose_kernel(const void* __restrict__ rawv) {
    __shared__ unsigned char tile[32][33];
    int b = blockIdx.z;
    int i0 = blockIdx.x * 32, j0 = blockIdx.y * 32;
    int tx = threadIdx.x, ty = threadIdx.y;
    int kind = g_mask_kind;
    size_t src = ((size_t)b * Nn + (j0 + ty)) * Nn + (i0 + tx);
    unsigned char v;
    if (kind == 0)      v = (((const unsigned char*)rawv)[src] != 0);
    else if (kind == 1) v = (((const int*)rawv)[src] != 0);
    else                v = (((const float*)rawv)[src] != 0.f);
    tile[ty][tx] = v;
    __syncthreads();
    g_maskT[((size_t)b * Nn + (i0 + ty)) * Nn + (j0 + tx)] = tile[tx][ty];
}

// ---------------- gemm: Y[row,f] = sum_e X[row,e] * W[f,e]   (rows=8192, E=256) ----------------
__global__ __launch_bounds__(256) void gemm_xw_kernel(const float* __restrict__ X,
                                                      const float* __restrict__ W,
                                                      float* __restrict__ Y) {
    __shared__ float As[64][65];
    __shared__ float Bs[64][65];
    int t = threadIdx.x;
    int row0 = blockIdx.x * 64;
    int col0 = blockIdx.y * 64;
    int rgp = t >> 4;
    int cg  = t & 15;
    ull acc[4][2];
#pragma unroll
    for (int r = 0; r < 4; r++) { acc[r][0] = 0ULL; acc[r][1] = 0ULL; }

    for (int k0 = 0; k0 < Ee; k0 += 64) {
#pragma unroll
        for (int q = 0; q < 4; q++) {
            int idx = t + q * 256;
            int r = idx >> 4, e4 = (idx & 15) * 4;
            float4 v = *(const float4*)(X + (size_t)(row0 + r) * Ee + k0 + e4);
            As[r][e4 + 0] = v.x; As[r][e4 + 1] = v.y; As[r][e4 + 2] = v.z; As[r][e4 + 3] = v.w;
        }
#pragma unroll
        for (int q = 0; q < 4; q++) {
            int idx = t + q * 256;
            int f = idx >> 4, e4 = (idx & 15) * 4;
            float4 v = *(const float4*)(W + (size_t)(col0 + f) * Ee + k0 + e4);
            Bs[e4 + 0][f] = v.x; Bs[e4 + 1][f] = v.y; Bs[e4 + 2][f] = v.z; Bs[e4 + 3][f] = v.w;
        }
        __syncthreads();
#pragma unroll 8
        for (int k = 0; k < 64; k++) {
            float b0 = Bs[k][cg * 4 + 0], b1 = Bs[k][cg * 4 + 1];
            float b2 = Bs[k][cg * 4 + 2], b3 = Bs[k][cg * 4 + 3];
            ull blo = pack2(b0, b1);
            ull bhi = pack2(b2, b3);
#pragma unroll
            for (int r = 0; r < 4; r++) {
                float a = As[rgp * 4 + r][k];
                ull a2 = pack2(a, a);
                acc[r][0] = ffma2(a2, blo, acc[r][0]);
                acc[r][1] = ffma2(a2, bhi, acc[r][1]);
            }
        }
        __syncthreads();
    }
#pragma unroll
    for (int r = 0; r < 4; r++) {
        float2 lo = unpack2(acc[r][0]);
        float2 hi = unpack2(acc[r][1]);
        float4 o = make_float4(lo.x, lo.y, hi.x, hi.y);
        *(float4*)(Y + (size_t)(row0 + rgp * 4 + r) * Ee + col0 + cg * 4) = o;
    }
}

// ---------------- K4: softmax denominator l[b,o,i] = sum_j exp(score) (no max needed) ----------------
__global__ __launch_bounds__(256) void stats_kernel(const float* __restrict__ u,
                                                    const float* __restrict__ u_w,
                                                    const float* __restrict__ u_b) {
    int i = blockIdx.x, b = blockIdx.y, t = threadIdx.x;
    __shared__ ull s_w2[48];
    __shared__ ull s_b2[8];
    __shared__ float s_red[8][9];
    if (t < 48) { float w = u_w[t]; s_w2[t] = pack2(w, w); }
    if (t < 8)  { float bb = u_b[t]; s_b2[t] = pack2(bb, bb); }
    __syncthreads();

    int j0 = t * 4;
    unsigned mword = *(const unsigned*)(g_maskT + ((size_t)b * Nn + i) * Nn + j0);
    bool m0 = (mword & 0xFFu) != 0, m1 = ((mword >> 8) & 0xFFu) != 0;
    bool m2 = ((mword >> 16) & 0xFFu) != 0, m3 = ((mword >> 24) & 0xFFu) != 0;

    ulonglong2 u2[Uu];
#pragma unroll
    for (int c = 0; c < Uu; c++)
        u2[c] = *(const ulonglong2*)(u + ((size_t)(b * Uu + c) * Nn + i) * Nn + j0);

    float l[Oo];
#pragma unroll
    for (int o = 0; o < Oo; o++) {
        ull sa = s_b2[o], sb = s_b2[o];
#pragma unroll
        for (int c = 0; c < Uu; c++) {
            sa = ffma2(s_w2[o * Uu + c], u2[c].x, sa);
            sb = ffma2(s_w2[o * Uu + c], u2[c].y, sb);
        }
        float2 f0 = unpack2(sa), f1 = unpack2(sb);
        float acc = 0.f;
        if (!m0) acc += __expf(f0.x);
        if (!m1) acc += __expf(f0.y);
        if (!m2) acc += __expf(f1.x);
        if (!m3) acc += __expf(f1.y);
        l[o] = acc;
    }
#pragma unroll
    for (int o = 0; o < Oo; o++)
#pragma unroll
        for (int st = 16; st > 0; st >>= 1)
            l[o] += __shfl_xor_sync(0xFFFFFFFFu, l[o], st);
    int w = t >> 5, lane = t & 31;
    if (lane == 0) {
#pragma unroll
        for (int o = 0; o < Oo; o++) s_red[o][w] = l[o];
    }
    __syncthreads();
    if (t < 8) {
        float s = 0.f;
#pragma unroll
        for (int w2 = 0; w2 < 8; w2++) s += s_red[t][w2];
        g_l[((size_t)b * Oo + t) * Nn + i] = s;
    }
}

// ---------------- K5: fused attn_w compute + write + (attn_w @ v) accumulate ----------------
// block = (b, 64-row i strip), 512 threads, loop over 16 j-tiles of 64.
// smem floats: s_w2[96] s_b2[16] beta[1..16pad] s_rl[512] As[4*64*65] Vs[64*256]
#define SM_W2   0
#define SM_B2   96
#define SM_BETA 112
#define SM_RL   128
#define SM_AS   640
#define SM_VS   17280
#define SM_TOT  33664   // floats -> 134656 bytes

__global__ __launch_bounds__(512, 1) void fused_kernel(const float* __restrict__ u,
                                                       const float* __restrict__ u_w,
                                                       const float* __restrict__ u_b,
                                                       float* __restrict__ attn_out) {
    extern __shared__ float sm[];
    ull*   s_w2   = (ull*)(sm + SM_W2);
    ull*   s_b2   = (ull*)(sm + SM_B2);
    float* s_beta = sm + SM_BETA;
    float* s_rl   = sm + SM_RL;
    float* As     = sm + SM_AS;    // [h*64 + j][65] row = j-major, col = i (pad 65)
    float* Vs     = sm + SM_VS;    // [j][256]

    int t = threadIdx.x;
    int b = blockIdx.y;
    int i0 = blockIdx.x * 64;

    if (t < 48)      { float w = u_w[t]; s_w2[t] = pack2(w, w); }
    else if (t < 56) { float bb = u_b[t - 48]; s_b2[t - 48] = pack2(bb, bb); }
    else if (t == 56) *s_beta = g_beta;
    {
        int o = t >> 6, il = t & 63;
        s_rl[t] = 1.0f / g_l[((size_t)b * Oo + o) * Nn + i0 + il];
    }
    __syncthreads();

    // phase A mapping
    const int jq = t & 15, iq = t >> 4;        // iq 0..31
    // phase B mapping
    const int ig = t & 31, dg = t >> 5;        // dg 0..15
    const int d0 = dg * 16;
    const int h_b = dg >> 2;
    const float beta = *s_beta;

    ull acc0[8], acc1[8];
#pragma unroll
    for (int k = 0; k < 8; k++) { acc0[k] = 0ULL; acc1[k] = 0ULL; }

    for (int jt0 = 0; jt0 < Nn; jt0 += 64) {
        // ---- load V tile [64][256] ----
#pragma unroll
        for (int q = 0; q < 8; q++) {
            int idx = t + q * 512;
            int r = idx >> 6, c = (idx & 63) * 4;
            *(float4*)&Vs[r * 256 + c] =
                *(const float4*)(g_v + ((size_t)b * Nn + jt0 + r) * Ee + c);
        }
        // ---- phase A: compute attn tile, write gmem + smem ----
#pragma unroll
        for (int r = 0; r < 2; r++) {
            int il = iq * 2 + r;
            int gi = i0 + il;
            int j0 = jt0 + jq * 4;
            unsigned mword = *(const unsigned*)(g_maskT + ((size_t)b * Nn + gi) * Nn + j0);
            bool m0 = (mword & 0xFFu) != 0, m1 = ((mword >> 8) & 0xFFu) != 0;
            bool m2 = ((mword >> 16) & 0xFFu) != 0, m3 = ((mword >> 24) & 0xFFu) != 0;
            ulonglong2 u2[Uu];
#pragma unroll
            for (int c = 0; c < Uu; c++)
                u2[c] = *(const ulonglong2*)(u + ((size_t)(b * Uu + c) * Nn + gi) * Nn + j0);
            int jb = jq * 4;
#pragma unroll
            for (int h = 0; h < Hh; h++) {
                int o0 = 2 * h, o1 = 2 * h + 1;
                ull sa0 = s_b2[o0], sb0 = s_b2[o0];
                ull sa1 = s_b2[o1], sb1 = s_b2[o1];
#pragma unroll
                for (int c = 0; c < Uu; c++) {
                    sa0 = ffma2(s_w2[o0 * Uu + c], u2[c].x, sa0);
                    sb0 = ffma2(s_w2[o0 * Uu + c], u2[c].y, sb0);
                    sa1 = ffma2(s_w2[o1 * Uu + c], u2[c].x, sa1);
                    sb1 = ffma2(s_w2[o1 * Uu + c], u2[c].y, sb1);
                }
                float2 f00 = unpack2(sa0), f01 = unpack2(sb0);
                float2 f10 = unpack2(sa1), f11 = unpack2(sb1);
                float rl0 = s_rl[o0 * 64 + il];
                float rl1 = s_rl[o1 * 64 + il];
                float p00 = m0 ? 0.f : __expf(f00.x) * rl0;
                float p01 = m1 ? 0.f : __expf(f00.y) * rl0;
                float p02 = m2 ? 0.f : __expf(f01.x) * rl0;
                float p03 = m3 ? 0.f : __expf(f01.y) * rl0;
                float p10 = m0 ? 0.f : __expf(f10.x) * rl1;
                float p11 = m1 ? 0.f : __expf(f10.y) * rl1;
                float p12 = m2 ? 0.f : __expf(f11.x) * rl1;
                float p13 = m3 ? 0.f : __expf(f11.y) * rl1;
                float a0 = p00 - beta * p10;
                float a1 = p01 - beta * p11;
                float a2 = p02 - beta * p12;
                float a3 = p03 - beta * p13;
                *(float4*)(attn_out + ((size_t)(b * Hh + h) * Nn + gi) * Nn + j0) =
                    make_float4(a0, a1, a2, a3);
                As[(h * 64 + jb + 0) * 65 + il] = a0;
                As[(h * 64 + jb + 1) * 65 + il] = a1;
                As[(h * 64 + jb + 2) * 65 + il] = a2;
                As[(h * 64 + jb + 3) * 65 + il] = a3;
            }
        }
        __syncthreads();
        // ---- phase B: acc += As(h_b) @ Vs ----
#pragma unroll 2
        for (int j4 = 0; j4 < 64; j4 += 4) {
#pragma unroll
            for (int q = 0; q < 4; q++) {
                int j = j4 + q;
                const ulonglong2* vp = (const ulonglong2*)&Vs[j * 256 + d0];
                ulonglong2 va = vp[0], vb = vp[1], vc = vp[2], vd = vp[3];
                float a0 = As[(h_b * 64 + j) * 65 + ig * 2];
                float a1 = As[(h_b * 64 + j) * 65 + ig * 2 + 1];
                ull a02 = pack2(a0, a0);
                ull a12 = pack2(a1, a1);
                acc0[0] = ffma2(a02, va.x, acc0[0]); acc0[1] = ffma2(a02, va.y, acc0[1]);
                acc0[2] = ffma2(a02, vb.x, acc0[2]); acc0[3] = ffma2(a02, vb.y, acc0[3]);
                acc0[4] = ffma2(a02, vc.x, acc0[4]); acc0[5] = ffma2(a02, vc.y, acc0[5]);
                acc0[6] = ffma2(a02, vd.x, acc0[6]); acc0[7] = ffma2(a02, vd.y, acc0[7]);
                acc1[0] = ffma2(a12, va.x, acc1[0]); acc1[1] = ffma2(a12, va.y, acc1[1]);
                acc1[2] = ffma2(a12, vb.x, acc1[2]); acc1[3] = ffma2(a12, vb.y, acc1[3]);
                acc1[4] = ffma2(a12, vc.x, acc1[4]); acc1[5] = ffma2(a12, vc.y, acc1[5]);
                acc1[6] = ffma2(a12, vd.x, acc1[6]); acc1[7] = ffma2(a12, vd.y, acc1[7]);
            }
        }
        __syncthreads();
    }
    // epilogue: write out_pre[b][i][d0..d0+15]
#pragma unroll
    for (int rr = 0; rr < 2; rr++) {
        int gi = i0 + ig * 2 + rr;
        float* op = g_outpre + ((size_t)b * Nn + gi) * Ee + d0;
        ull* ap = rr ? acc1 : acc0;
#pragma unroll
        for (int k4 = 0; k4 < 4; k4++) {
            ulonglong2 st;
            st.x = ap[2 * k4]; st.y = ap[2 * k4 + 1];
            *(ulonglong2*)(op + k4 * 4) = st;
        }
    }
}

// ---------------- launch ----------------
extern "C" void kernel_launch(void* const* d_in, const int* in_sizes, int n_in,
                              void* d_out, int out_size) {
    const float* x     = (const float*)d_in[0];
    const float* u     = (const float*)d_in[1];
    const void*  umask = d_in[2];
    const float* v_w   = (const float*)d_in[3];
    const float* out_w = (const float*)d_in[4];
    const float* u_w   = (const float*)d_in[5];
    const float* u_b   = (const float*)d_in[6];
    const float* lq    = (const float*)d_in[7];
    const float* lk    = (const float*)d_in[8];

    float* out = (float*)d_out;
    const size_t OUT_ELEMS  = (size_t)Bb * Nn * Ee;          // 2097152
    const size_t ATTN_ELEMS = (size_t)Bb * Hh * Nn * Nn;     // 33554432
    float* attn_out  = out + OUT_ELEMS;
    float* beta_slot = out + OUT_ELEMS + ATTN_ELEMS;

    float* vptr = nullptr;
    float* optr = nullptr;
    cudaGetSymbolAddress((void**)&vptr, g_v);
    cudaGetSymbolAddress((void**)&optr, g_outpre);

    static bool attr_set = false;
    if (!attr_set) {
        cudaFuncSetAttribute(fused_kernel, cudaFuncAttributeMaxDynamicSharedMemorySize,
                             SM_TOT * 4);
        attr_set = true;
    }

    beta_kernel<<<1, 128>>>(lq, lk, beta_slot);
    detect_kernel<<<1, 256>>>((const unsigned char*)umask);
    mask_transpose_kernel<<<dim3(32, 32, 8), dim3(32, 32)>>>(umask);
    gemm_xw_kernel<<<dim3(128, 4), 256>>>(x, v_w, vptr);                // v projection
    stats_kernel<<<dim3(Nn, Bb), 256>>>(u, u_w, u_b);
    fused_kernel<<<dim3(16, 8), 512, SM_TOT * 4>>>(u, u_w, u_b, attn_out);
    gemm_xw_kernel<<<dim3(128, 4), 256>>>(optr, out_w, out);            // output projection
    (void)in_sizes; (void)n_in; (void)out_size;
}